// round 1
// baseline (speedup 1.0000x reference)
#include <cuda_runtime.h>

#define IN_C  64
#define OUT_C 64
#define HH    112
#define WW    112
#define NB    2

// Tile config: block = 128 threads
//   thread: cg = tid&3 (4 cols each), rr = (tid>>2)&3 (row), ocg = tid>>4 (8 oc each)
//   block tile: 4 rows x 16 cols x 64 oc
//   grid: (112/16=7, 112/4=28, 2) = 392 blocks
#define TH 4
#define TW 16
#define ICB 8   // input channels staged per iteration

__global__ __launch_bounds__(128, 4)
void conv3x3_kernel(const float* __restrict__ x,
                    const float* __restrict__ wgt,
                    const float* __restrict__ bias,
                    float* __restrict__ out)
{
    const int tid = threadIdx.x;
    const int cg  = tid & 3;          // column group (4 cols)
    const int rr  = (tid >> 2) & 3;   // row within tile
    const int ocg = tid >> 4;         // 0..7 -> 8 output channels each

    const int col0 = blockIdx.x * TW;
    const int row0 = blockIdx.y * TH;
    const int b    = blockIdx.z;

    // ws: [ic (ICB)][tap (9)][oc (64)]  -> float4 loads over oc, broadcast in warp
    __shared__ __align__(16) float ws[ICB * 9 * 64];      // 18432 B
    // xs: [ic (ICB)][r (6)][c stride 19, 18 used]        // stride 19 => conflict-free
    __shared__ __align__(16) float xs[ICB * 6 * 19];      //  3648 B

    float acc[4][8];
    #pragma unroll
    for (int o = 0; o < 8; ++o) {
        const float bv = __ldg(&bias[ocg * 8 + o]);
        #pragma unroll
        for (int s = 0; s < 4; ++s) acc[s][o] = bv;
    }

    for (int ic0 = 0; ic0 < IN_C; ic0 += ICB) {
        __syncthreads();

        // ---- stage weights: 64 oc * ICB ic * 9 taps = 4608 elements ----
        #pragma unroll
        for (int e = tid; e < 64 * ICB * 9; e += 128) {
            const int oc  = e / (ICB * 9);
            const int rem = e % (ICB * 9);
            const int ic  = rem / 9;
            const int k   = rem % 9;
            ws[(ic * 9 + k) * 64 + oc] =
                wgt[(oc * IN_C + ic0 + ic) * 9 + k];
        }

        // ---- stage input tile: ICB ic * 6 rows * 18 cols = 864 elements ----
        for (int e = tid; e < ICB * 6 * 18; e += 128) {
            const int ic  = e / 108;
            const int rem = e % 108;
            const int r   = rem / 18;
            const int c   = rem % 18;
            const int gr  = row0 - 1 + r;
            const int gc  = col0 - 1 + c;
            float v = 0.0f;
            if ((unsigned)gr < (unsigned)HH && (unsigned)gc < (unsigned)WW)
                v = x[(((b * IN_C) + ic0 + ic) * HH + gr) * WW + gc];
            xs[(ic * 6 + r) * 19 + c] = v;
        }

        __syncthreads();

        // ---- compute ICB channels ----
        #pragma unroll 1
        for (int ic = 0; ic < ICB; ++ic) {
            // register patch: 3 rows x 6 cols
            float xp[3][6];
            #pragma unroll
            for (int r = 0; r < 3; ++r)
                #pragma unroll
                for (int c = 0; c < 6; ++c)
                    xp[r][c] = xs[(ic * 6 + rr + r) * 19 + cg * 4 + c];

            const float* wp = &ws[ic * 576 + ocg * 8];
            #pragma unroll
            for (int kh = 0; kh < 3; ++kh) {
                #pragma unroll
                for (int kw = 0; kw < 3; ++kw) {
                    const float4 w0 = *(const float4*)&wp[(kh * 3 + kw) * 64];
                    const float4 w1 = *(const float4*)&wp[(kh * 3 + kw) * 64 + 4];
                    #pragma unroll
                    for (int s = 0; s < 4; ++s) {
                        const float xv = xp[kh][kw + s];
                        acc[s][0] += xv * w0.x;
                        acc[s][1] += xv * w0.y;
                        acc[s][2] += xv * w0.z;
                        acc[s][3] += xv * w0.w;
                        acc[s][4] += xv * w1.x;
                        acc[s][5] += xv * w1.y;
                        acc[s][6] += xv * w1.z;
                        acc[s][7] += xv * w1.w;
                    }
                }
            }
        }
    }

    // ---- write out: 8 oc x one float4 row-segment each ----
    const int gy = row0 + rr;
    const int gx = col0 + cg * 4;
    #pragma unroll
    for (int o = 0; o < 8; ++o) {
        const int oc = ocg * 8 + o;
        float4 v = make_float4(acc[0][o], acc[1][o], acc[2][o], acc[3][o]);
        *(float4*)&out[(((b * OUT_C) + oc) * HH + gy) * WW + gx] = v;
    }
}

extern "C" void kernel_launch(void* const* d_in, const int* in_sizes, int n_in,
                              void* d_out, int out_size)
{
    const float* x    = (const float*)d_in[0];
    const float* wgt  = (const float*)d_in[1];
    const float* bias = (const float*)d_in[2];
    float* out        = (float*)d_out;

    dim3 grid(WW / TW, HH / TH, NB);   // (7, 28, 2) = 392 blocks
    dim3 block(128);
    conv3x3_kernel<<<grid, block>>>(x, wgt, bias, out);
}

// round 3
// speedup vs baseline: 2.9783x; 2.9783x over previous
#include <cuda_runtime.h>
#include <cuda_bf16.h>
#include <cstdint>

#define IN_C  64
#define OUT_C 64
#define HH    112
#define WW    112
#define NB    2

#define TROWS 8
#define TCOLS 16
#define KTOT  576
#define KCH   64
#define NCHUNK 9

// raw tile: 64 ic x 10 rows x 18 cols (fp32)
#define RAW_R 10
#define RAW_C 18
#define RAW_PER_IC (RAW_R * RAW_C)      // 180
#define RAW_ELEMS  (IN_C * RAW_PER_IC)  // 11520

#define APAD 72     // bf16 elems per A row (144 B) -> conflict-free frag LDS
#define BPAD 72

// smem byte offsets
#define OFF_AH  0u
#define OFF_AL  18432u
#define OFF_BH  36864u
#define OFF_BL  46080u
#define OFF_RAW 55296u
#define OFF_LUT 101376u
#define OFF_BIAS 103680u
#define SMEM_BYTES 103936u

__device__ __forceinline__ void mma_bf16(float* d, const uint32_t* a, const uint32_t* b) {
    asm volatile(
        "mma.sync.aligned.m16n8k16.row.col.f32.bf16.bf16.f32 "
        "{%0,%1,%2,%3}, {%4,%5,%6,%7}, {%8,%9}, {%0,%1,%2,%3};"
        : "+f"(d[0]), "+f"(d[1]), "+f"(d[2]), "+f"(d[3])
        : "r"(a[0]), "r"(a[1]), "r"(a[2]), "r"(a[3]), "r"(b[0]), "r"(b[1]));
}

__device__ __forceinline__ uint32_t pack_hi(float v0, float v1) {
    __nv_bfloat162 h = { __float2bfloat16_rn(v0), __float2bfloat16_rn(v1) };
    return *(uint32_t*)&h;
}
__device__ __forceinline__ uint32_t pack_lo(float v0, float v1) {
    __nv_bfloat16 h0 = __float2bfloat16_rn(v0);
    __nv_bfloat16 h1 = __float2bfloat16_rn(v1);
    __nv_bfloat162 l = { __float2bfloat16_rn(v0 - __bfloat162float(h0)),
                         __float2bfloat16_rn(v1 - __bfloat162float(h1)) };
    return *(uint32_t*)&l;
}

__global__ void __launch_bounds__(256, 2)
conv3x3_hmma_kernel(const float* __restrict__ x,
                    const float* __restrict__ wgt,
                    const float* __restrict__ bias,
                    float* __restrict__ out)
{
    extern __shared__ char sm[];

    const int tid  = threadIdx.x;
    const int wid  = tid >> 5;
    const int lane = tid & 31;
    const int grp  = lane >> 2;     // 0..7
    const int tid4 = lane & 3;      // 0..3

    const int wm = wid & 3;         // warp m-group (4 x 32 rows)
    const int wn = wid >> 2;        // warp n-group (2 x 32 cols)

    const int col0 = blockIdx.x * TCOLS;
    const int row0 = blockIdx.y * TROWS;
    const int b    = blockIdx.z;

    float* rawf  = (float*)(sm + OFF_RAW);
    int*   lut   = (int*)(sm + OFF_LUT);
    float* biass = (float*)(sm + OFF_BIAS);

    // ---- stage raw x tile: 64 ic x 10 x 18 (zero-padded halo) ----
    for (int e = tid; e < RAW_ELEMS; e += 256) {
        const int ic  = e / RAW_PER_IC;
        const int rem = e - ic * RAW_PER_IC;
        const int r   = rem / RAW_C;
        const int c   = rem - r * RAW_C;
        const int gr  = row0 - 1 + r;
        const int gc  = col0 - 1 + c;
        float v = 0.0f;
        if ((unsigned)gr < (unsigned)HH && (unsigned)gc < (unsigned)WW)
            v = x[(((b * IN_C) + ic) * HH + gr) * WW + gc];
        rawf[e] = v;
    }
    // ---- full K offset LUT (576 entries) ----
    for (int e = tid; e < KTOT; e += 256) {
        const int ic  = e / 9;
        const int tap = e - ic * 9;
        const int dy  = tap / 3;
        const int dx  = tap - dy * 3;
        lut[e] = ic * RAW_PER_IC + dy * RAW_C + dx;
    }
    if (tid < OUT_C) biass[tid] = bias[tid];

    // accumulators: [m-frag 2][n-frag 4][4]
    float acc[2][4][4];
    #pragma unroll
    for (int f = 0; f < 2; ++f)
        #pragma unroll
        for (int g = 0; g < 4; ++g)
            #pragma unroll
            for (int q = 0; q < 4; ++q) acc[f][g][q] = 0.0f;

    // A/B build thread mapping (same for every chunk)
    const int mg = wid * 4 + (lane >> 3);   // 0..31
    const int u  = lane & 7;                // 0..7 (8-k unit)

    const uint32_t* Ahw = (const uint32_t*)(sm + OFF_AH);
    const uint32_t* Alw = (const uint32_t*)(sm + OFF_AL);
    const uint32_t* Bhw = (const uint32_t*)(sm + OFF_BH);
    const uint32_t* Blw = (const uint32_t*)(sm + OFF_BL);

    for (int chunk = 0; chunk < NCHUNK; ++chunk) {
        __syncthreads();   // prior mma reads done (also covers raw/lut staging)

        // per-thread K offsets for its 8-k unit
        int o[8];
        #pragma unroll
        for (int t = 0; t < 8; ++t) o[t] = lut[chunk * KCH + u * 8 + t];

        // ---- build A_hi / A_lo: 128m x 64k, padded rows ----
        #pragma unroll
        for (int j = 0; j < 4; ++j) {
            const int m    = j * 32 + mg;
            const int base = (m >> 4) * RAW_C + (m & 15);
            float v[8];
            #pragma unroll
            for (int t = 0; t < 8; ++t) v[t] = rawf[base + o[t]];
            uint32_t hp[4], lp[4];
            #pragma unroll
            for (int t = 0; t < 4; ++t) {
                hp[t] = pack_hi(v[2 * t], v[2 * t + 1]);
                lp[t] = pack_lo(v[2 * t], v[2 * t + 1]);
            }
            const uint32_t byte = (uint32_t)m * (APAD * 2) + (uint32_t)u * 16u;
            *(uint4*)(sm + OFF_AH + byte) = *(uint4*)hp;
            *(uint4*)(sm + OFF_AL + byte) = *(uint4*)lp;
        }

        // ---- build B_hi / B_lo: 64n x 64k (B[n][k] = wgt[oc*576 + k]) ----
        #pragma unroll
        for (int j = 0; j < 2; ++j) {
            const int oc = j * 32 + mg;
            const float4 w0 = *(const float4*)&wgt[oc * KTOT + chunk * KCH + u * 8];
            const float4 w1 = *(const float4*)&wgt[oc * KTOT + chunk * KCH + u * 8 + 4];
            uint32_t hp[4], lp[4];
            hp[0] = pack_hi(w0.x, w0.y); lp[0] = pack_lo(w0.x, w0.y);
            hp[1] = pack_hi(w0.z, w0.w); lp[1] = pack_lo(w0.z, w0.w);
            hp[2] = pack_hi(w1.x, w1.y); lp[2] = pack_lo(w1.x, w1.y);
            hp[3] = pack_hi(w1.z, w1.w); lp[3] = pack_lo(w1.z, w1.w);
            const uint32_t byte = (uint32_t)oc * (BPAD * 2) + (uint32_t)u * 16u;
            *(uint4*)(sm + OFF_BH + byte) = *(uint4*)hp;
            *(uint4*)(sm + OFF_BL + byte) = *(uint4*)lp;
        }

        __syncthreads();

        // ---- MMA: 4 k16-steps, 3 passes ----
        #pragma unroll
        for (int ks = 0; ks < 4; ++ks) {
            uint32_t ah[2][4], al[2][4], bh[4][2], bl[4][2];
            #pragma unroll
            for (int f = 0; f < 2; ++f) {
                const int r0 = wm * 32 + f * 16 + grp;
                const int w0i = r0 * (APAD / 2) + ks * 8 + tid4;       // word index
                const int w1i = (r0 + 8) * (APAD / 2) + ks * 8 + tid4;
                ah[f][0] = Ahw[w0i];     ah[f][1] = Ahw[w1i];
                ah[f][2] = Ahw[w0i + 4]; ah[f][3] = Ahw[w1i + 4];
                al[f][0] = Alw[w0i];     al[f][1] = Alw[w1i];
                al[f][2] = Alw[w0i + 4]; al[f][3] = Alw[w1i + 4];
            }
            #pragma unroll
            for (int g = 0; g < 4; ++g) {
                const int n  = wn * 32 + g * 8 + grp;
                const int wi = n * (BPAD / 2) + ks * 8 + tid4;
                bh[g][0] = Bhw[wi]; bh[g][1] = Bhw[wi + 4];
                bl[g][0] = Blw[wi]; bl[g][1] = Blw[wi + 4];
            }
            #pragma unroll
            for (int f = 0; f < 2; ++f)
                #pragma unroll
                for (int g = 0; g < 4; ++g) {
                    mma_bf16(acc[f][g], ah[f], bh[g]);
                    mma_bf16(acc[f][g], ah[f], bl[g]);
                    mma_bf16(acc[f][g], al[f], bh[g]);
                }
        }
    }

    // ---- epilogue: bias + store ----
    #pragma unroll
    for (int f = 0; f < 2; ++f) {
        const int m0 = wm * 32 + f * 16 + grp;
        #pragma unroll
        for (int half = 0; half < 2; ++half) {
            const int m  = m0 + half * 8;
            const int gy = row0 + (m >> 4);
            const int gx = col0 + (m & 15);
            float* op = &out[((b * OUT_C) * HH + gy) * WW + gx];
            #pragma unroll
            for (int g = 0; g < 4; ++g) {
                const int n = wn * 32 + g * 8 + tid4 * 2;
                op[n * (HH * WW)]       = acc[f][g][half * 2]     + biass[n];
                op[(n + 1) * (HH * WW)] = acc[f][g][half * 2 + 1] + biass[n + 1];
            }
        }
    }
}

extern "C" void kernel_launch(void* const* d_in, const int* in_sizes, int n_in,
                              void* d_out, int out_size)
{
    const float* x    = (const float*)d_in[0];
    const float* wgt  = (const float*)d_in[1];
    const float* bias = (const float*)d_in[2];
    float* out        = (float*)d_out;

    cudaFuncSetAttribute(conv3x3_hmma_kernel,
                         cudaFuncAttributeMaxDynamicSharedMemorySize, SMEM_BYTES);

    dim3 grid(WW / TCOLS, HH / TROWS, NB);   // (7, 14, 2) = 196 CTAs
    conv3x3_hmma_kernel<<<grid, 256, SMEM_BYTES>>>(x, wgt, bias, out);
}

// round 4
// speedup vs baseline: 3.3147x; 1.1129x over previous
#include <cuda_runtime.h>
#include <cuda_bf16.h>
#include <cstdint>

#define IN_C  64
#define OUT_C 64
#define HH    112
#define WW    112
#define NB    2

#define TROWS 4
#define TCOLS 16
#define KTOT  576
#define KCH   64
#define NCHUNK 9

// raw tile: 64 ic x 6 rows x 18 cols (fp32)
#define RAW_R 6
#define RAW_C 18
#define RAW_PER_IC (RAW_R * RAW_C)      // 108
#define RAW_ELEMS  (IN_C * RAW_PER_IC)  // 6912

#define APAD 72     // bf16 elems per row (144 B) -> conflict-free frag LDS

// smem byte offsets
#define OFF_AH  0u          // 64 x 144B = 9216
#define OFF_AL  9216u
#define OFF_BH  18432u      // 64 x 144B
#define OFF_BL  27648u
#define OFF_RAW 36864u      // 27648 B
#define OFF_LUT 64512u      // 2304 B
#define OFF_BIAS 66816u     // 256 B
#define SMEM_BYTES 67072u

// pre-converted weights: [chunk 9][n 64][k 64] bf16
__device__ __align__(16) __nv_bfloat16 Bh_g[NCHUNK * 64 * KCH];
__device__ __align__(16) __nv_bfloat16 Bl_g[NCHUNK * 64 * KCH];

__device__ __forceinline__ void mma_bf16(float* d, const uint32_t* a, const uint32_t* b) {
    asm volatile(
        "mma.sync.aligned.m16n8k16.row.col.f32.bf16.bf16.f32 "
        "{%0,%1,%2,%3}, {%4,%5,%6,%7}, {%8,%9}, {%0,%1,%2,%3};"
        : "+f"(d[0]), "+f"(d[1]), "+f"(d[2]), "+f"(d[3])
        : "r"(a[0]), "r"(a[1]), "r"(a[2]), "r"(a[3]), "r"(b[0]), "r"(b[1]));
}

__device__ __forceinline__ uint32_t pack_hi(float v0, float v1) {
    __nv_bfloat162 h = { __float2bfloat16_rn(v0), __float2bfloat16_rn(v1) };
    return *(uint32_t*)&h;
}
__device__ __forceinline__ uint32_t pack_lo(float v0, float v1) {
    __nv_bfloat16 h0 = __float2bfloat16_rn(v0);
    __nv_bfloat16 h1 = __float2bfloat16_rn(v1);
    __nv_bfloat162 l = { __float2bfloat16_rn(v0 - __bfloat162float(h0)),
                         __float2bfloat16_rn(v1 - __bfloat162float(h1)) };
    return *(uint32_t*)&l;
}

// ---- pre-kernel: split weights to bf16 hi/lo, chunked layout ----
__global__ void __launch_bounds__(256)
prep_weights_kernel(const float* __restrict__ wgt)
{
    const int i = blockIdx.x * 256 + threadIdx.x;
    if (i >= NCHUNK * 64 * KCH) return;
    const int chunk = i >> 12;
    const int rem   = i & 4095;
    const int n     = rem >> 6;
    const int kk    = rem & 63;
    const float v = wgt[n * KTOT + chunk * KCH + kk];
    const __nv_bfloat16 h = __float2bfloat16_rn(v);
    Bh_g[i] = h;
    Bl_g[i] = __float2bfloat16_rn(v - __bfloat162float(h));
}

// ---- main kernel ----
__global__ void __launch_bounds__(256, 3)
conv3x3_hmma_kernel(const float* __restrict__ x,
                    const float* __restrict__ bias,
                    float* __restrict__ out)
{
    extern __shared__ char sm[];

    const int tid  = threadIdx.x;
    const int wid  = tid >> 5;
    const int lane = tid & 31;
    const int grp  = lane >> 2;     // 0..7
    const int tid4 = lane & 3;      // 0..3

    const int wm = wid & 3;         // warp m-group (4 x 16 rows)
    const int wn = wid >> 2;        // warp n-group (2 x 32 cols)

    const int col0 = blockIdx.x * TCOLS;
    const int row0 = blockIdx.y * TROWS;
    const int b    = blockIdx.z;

    float* rawf  = (float*)(sm + OFF_RAW);
    int*   lut   = (int*)(sm + OFF_LUT);
    float* biass = (float*)(sm + OFF_BIAS);

    // ---- stage raw x tile: 64 ic x 6 x 18 (zero-padded halo) ----
    for (int e = tid; e < RAW_ELEMS; e += 256) {
        const int ic  = e / RAW_PER_IC;
        const int rem = e - ic * RAW_PER_IC;
        const int r   = rem / RAW_C;
        const int c   = rem - r * RAW_C;
        const int gr  = row0 - 1 + r;
        const int gc  = col0 - 1 + c;
        float v = 0.0f;
        if ((unsigned)gr < (unsigned)HH && (unsigned)gc < (unsigned)WW)
            v = x[(((b * IN_C) + ic) * HH + gr) * WW + gc];
        rawf[e] = v;
    }
    // ---- K offset LUT ----
    for (int e = tid; e < KTOT; e += 256) {
        const int ic  = e / 9;
        const int tap = e - ic * 9;
        const int dy  = tap / 3;
        const int dx  = tap - dy * 3;
        lut[e] = ic * RAW_PER_IC + dy * RAW_C + dx;
    }
    if (tid < OUT_C) biass[tid] = bias[tid];

    // accumulators: [n-frag 4][4]
    float acc[4][4];
    #pragma unroll
    for (int g = 0; g < 4; ++g)
        #pragma unroll
        for (int q = 0; q < 4; ++q) acc[g][q] = 0.0f;

    // A build mapping: 256 threads -> 32 rows x 8 k-units per pass
    const int mg = tid >> 3;        // 0..31
    const int u  = tid & 7;         // 0..7

    const uint32_t* Ahw = (const uint32_t*)(sm + OFF_AH);
    const uint32_t* Alw = (const uint32_t*)(sm + OFF_AL);
    const uint32_t* Bhw = (const uint32_t*)(sm + OFF_BH);
    const uint32_t* Blw = (const uint32_t*)(sm + OFF_BL);

    for (int chunk = 0; chunk < NCHUNK; ++chunk) {
        __syncthreads();   // staging done / previous MMA reads done

        int o[8];
        #pragma unroll
        for (int t = 0; t < 8; ++t) o[t] = lut[chunk * KCH + u * 8 + t];

        // ---- build A_hi / A_lo: 64m x 64k ----
        #pragma unroll
        for (int j = 0; j < 2; ++j) {
            const int m    = j * 32 + mg;
            const int base = (m >> 4) * RAW_C + (m & 15);
            float v[8];
            #pragma unroll
            for (int t = 0; t < 8; ++t) v[t] = rawf[base + o[t]];
            uint32_t hp[4], lp[4];
            #pragma unroll
            for (int t = 0; t < 4; ++t) {
                hp[t] = pack_hi(v[2 * t], v[2 * t + 1]);
                lp[t] = pack_lo(v[2 * t], v[2 * t + 1]);
            }
            const uint32_t byte = (uint32_t)m * (APAD * 2) + (uint32_t)u * 16u;
            *(uint4*)(sm + OFF_AH + byte) = *(uint4*)hp;
            *(uint4*)(sm + OFF_AL + byte) = *(uint4*)lp;
        }

        // ---- copy pre-converted B tiles (bf16, no math) ----
        {
            const uint4* bsh = ((const uint4*)Bh_g) + chunk * 512;
            const uint4* bsl = ((const uint4*)Bl_g) + chunk * 512;
            #pragma unroll
            for (int e = tid; e < 512; e += 256) {
                const uint32_t dst = (uint32_t)(e >> 3) * (APAD * 2) + (uint32_t)(e & 7) * 16u;
                *(uint4*)(sm + OFF_BH + dst) = bsh[e];
                *(uint4*)(sm + OFF_BL + dst) = bsl[e];
            }
        }

        __syncthreads();

        // ---- MMA: 4 k16-steps, 3 passes (Ah*Bh + Ah*Bl + Al*Bh) ----
        #pragma unroll
        for (int ks = 0; ks < 4; ++ks) {
            uint32_t ah[4], al[4];
            const int r0  = wm * 16 + grp;
            const int w0i = r0 * (APAD / 2) + ks * 8 + tid4;
            const int w1i = w0i + 8 * (APAD / 2);
            ah[0] = Ahw[w0i];     ah[1] = Ahw[w1i];
            ah[2] = Ahw[w0i + 4]; ah[3] = Ahw[w1i + 4];
            al[0] = Alw[w0i];     al[1] = Alw[w1i];
            al[2] = Alw[w0i + 4]; al[3] = Alw[w1i + 4];

            #pragma unroll
            for (int g = 0; g < 4; ++g) {
                const int n  = wn * 32 + g * 8 + grp;
                const int wi = n * (APAD / 2) + ks * 8 + tid4;
                uint32_t bh[2], bl[2];
                bh[0] = Bhw[wi]; bh[1] = Bhw[wi + 4];
                bl[0] = Blw[wi]; bl[1] = Blw[wi + 4];
                mma_bf16(acc[g], ah, bh);
                mma_bf16(acc[g], ah, bl);
                mma_bf16(acc[g], al, bh);
            }
        }
    }

    // ---- epilogue: bias + store ----
    #pragma unroll
    for (int half = 0; half < 2; ++half) {
        const int gy = row0 + wm;
        const int gx = col0 + grp + half * 8;
        float* op = &out[((b * OUT_C) * HH + gy) * WW + gx];
        #pragma unroll
        for (int g = 0; g < 4; ++g) {
            const int n = wn * 32 + g * 8 + tid4 * 2;
            op[n * (HH * WW)]       = acc[g][half * 2]     + biass[n];
            op[(n + 1) * (HH * WW)] = acc[g][half * 2 + 1] + biass[n + 1];
        }
    }
}

extern "C" void kernel_launch(void* const* d_in, const int* in_sizes, int n_in,
                              void* d_out, int out_size)
{
    const float* x    = (const float*)d_in[0];
    const float* wgt  = (const float*)d_in[1];
    const float* bias = (const float*)d_in[2];
    float* out        = (float*)d_out;

    cudaFuncSetAttribute(conv3x3_hmma_kernel,
                         cudaFuncAttributeMaxDynamicSharedMemorySize, SMEM_BYTES);

    prep_weights_kernel<<<(NCHUNK * 64 * KCH + 255) / 256, 256>>>(wgt);

    dim3 grid(WW / TCOLS, HH / TROWS, NB);   // (7, 28, 2) = 392 CTAs
    conv3x3_hmma_kernel<<<grid, 256, SMEM_BYTES>>>(x, bias, out);
}

// round 5
// speedup vs baseline: 3.3319x; 1.0052x over previous
#include <cuda_runtime.h>
#include <cuda_bf16.h>
#include <cstdint>

#define IN_C  64
#define OUT_C 64
#define HH    112
#define WW    112
#define NB    2

#define TROWS 4
#define TCOLS 16
#define KTOT  576
#define KCH   64
#define NCHUNK 9

// raw tile: 64 ic x 6 rows x 18 cols (fp32)
#define RAW_R 6
#define RAW_C 18
#define RAW_PER_IC (RAW_R * RAW_C)      // 108
#define RAW_ELEMS  (IN_C * RAW_PER_IC)  // 6912

#define APAD 72          // bf16 elems per row (144 B)
#define ROWB (APAD * 2)  // 144 bytes per row

// smem byte offsets
#define OFF_AH  0u          // 64 x 144B = 9216
#define OFF_AL  9216u
#define OFF_BH  18432u
#define OFF_BL  27648u
#define OFF_RAW 36864u      // 27648 B
#define OFF_LUT 64512u      // 2304 B
#define OFF_BIAS 66816u
#define SMEM_BYTES 67072u

// pre-converted weights: [chunk 9][n 64][k 64] bf16
__device__ __align__(16) __nv_bfloat16 Bh_g[NCHUNK * 64 * KCH];
__device__ __align__(16) __nv_bfloat16 Bl_g[NCHUNK * 64 * KCH];

__device__ __forceinline__ uint32_t smem_u32(const void* p) {
    uint32_t a;
    asm("{ .reg .u64 t; cvta.to.shared.u64 t, %1; cvt.u32.u64 %0, t; }" : "=r"(a) : "l"(p));
    return a;
}

__device__ __forceinline__ void mma_bf16(float* d, const uint32_t* a, const uint32_t* b) {
    asm volatile(
        "mma.sync.aligned.m16n8k16.row.col.f32.bf16.bf16.f32 "
        "{%0,%1,%2,%3}, {%4,%5,%6,%7}, {%8,%9}, {%0,%1,%2,%3};"
        : "+f"(d[0]), "+f"(d[1]), "+f"(d[2]), "+f"(d[3])
        : "r"(a[0]), "r"(a[1]), "r"(a[2]), "r"(a[3]), "r"(b[0]), "r"(b[1]));
}

__device__ __forceinline__ void ldmx4(uint32_t* r, uint32_t addr) {
    asm volatile("ldmatrix.sync.aligned.m8n8.x4.shared.b16 {%0,%1,%2,%3}, [%4];"
        : "=r"(r[0]), "=r"(r[1]), "=r"(r[2]), "=r"(r[3]) : "r"(addr));
}

// truncation split: hi = high-16-bits of fp32 (packed via PRMT), lo = v - hi
__device__ __forceinline__ void split2(float v0, float v1, uint32_t& hp, uint32_t& lp) {
    const uint32_t u0 = __float_as_uint(v0);
    const uint32_t u1 = __float_as_uint(v1);
    uint32_t h;
    asm("prmt.b32 %0, %1, %2, 0x7632;" : "=r"(h) : "r"(u0), "r"(u1));
    hp = h;
    const float h0 = __uint_as_float(h << 16);
    const float h1 = __uint_as_float(h & 0xFFFF0000u);
    const float l0 = v0 - h0;
    const float l1 = v1 - h1;
    asm("cvt.rn.bf16x2.f32 %0, %1, %2;" : "=r"(lp) : "f"(l1), "f"(l0));
}

// ---- pre-kernel: split weights to bf16 hi/lo, chunked layout ----
__global__ void __launch_bounds__(256)
prep_weights_kernel(const float* __restrict__ wgt)
{
    const int i = blockIdx.x * 256 + threadIdx.x;
    if (i >= NCHUNK * 64 * KCH) return;
    const int chunk = i >> 12;
    const int rem   = i & 4095;
    const int n     = rem >> 6;
    const int kk    = rem & 63;
    const float v = wgt[n * KTOT + chunk * KCH + kk];
    const __nv_bfloat16 h = __float2bfloat16_rn(v);
    Bh_g[i] = h;
    Bl_g[i] = __float2bfloat16_rn(v - __bfloat162float(h));
}

// ---- main kernel ----
__global__ void __launch_bounds__(256, 3)
conv3x3_hmma_kernel(const float* __restrict__ x,
                    const float* __restrict__ bias,
                    float* __restrict__ out)
{
    extern __shared__ char sm[];
    const uint32_t sb = smem_u32(sm);

    const int tid  = threadIdx.x;
    const int wid  = tid >> 5;
    const int lane = tid & 31;
    const int grp  = lane >> 2;
    const int tid4 = lane & 3;

    const int wm = wid & 3;         // warp m-group (4 x 16 rows)
    const int wn = wid >> 2;        // warp n-group (2 x 32 cols)

    const int col0 = blockIdx.x * TCOLS;
    const int row0 = blockIdx.y * TROWS;
    const int b    = blockIdx.z;

    float* rawf  = (float*)(sm + OFF_RAW);
    int*   lut   = (int*)(sm + OFF_LUT);
    float* biass = (float*)(sm + OFF_BIAS);

    // ---- stage raw x tile: 64 ic x 6 x 18 (zero-padded halo) ----
    for (int e = tid; e < RAW_ELEMS; e += 256) {
        const int ic  = e / RAW_PER_IC;
        const int rem = e - ic * RAW_PER_IC;
        const int r   = rem / RAW_C;
        const int c   = rem - r * RAW_C;
        const int gr  = row0 - 1 + r;
        const int gc  = col0 - 1 + c;
        float v = 0.0f;
        if ((unsigned)gr < (unsigned)HH && (unsigned)gc < (unsigned)WW)
            v = x[(((b * IN_C) + ic) * HH + gr) * WW + gc];
        rawf[e] = v;
    }
    for (int e = tid; e < KTOT; e += 256) {
        const int ic  = e / 9;
        const int tap = e - ic * 9;
        const int dy  = tap / 3;
        const int dx  = tap - dy * 3;
        lut[e] = ic * RAW_PER_IC + dy * RAW_C + dx;
    }
    if (tid < OUT_C) biass[tid] = bias[tid];

    float acc[4][4];
    #pragma unroll
    for (int g = 0; g < 4; ++g)
        #pragma unroll
        for (int q = 0; q < 4; ++q) acc[g][q] = 0.0f;

    // A build mapping
    const int mg = tid >> 3;        // 0..31
    const int u  = tid & 7;         // 0..7

    // ---- ldmatrix per-lane base addresses ----
    // A: mat = lane>>3; mat&1 -> +8 rows, mat>>1 -> +16 k bytes
    const int matq = lane >> 3;
    const int rq   = lane & 7;
    const uint32_t aAh = sb + OFF_AH
        + (uint32_t)(wm * 16 + ((matq & 1) << 3) + rq) * ROWB
        + (uint32_t)((matq >> 1) << 4);
    const uint32_t aAl = aAh + (OFF_AL - OFF_AH);
    // B: mat&1 -> +16 k bytes, mat>>1 -> +8 n rows
    const uint32_t aBh = sb + OFF_BH
        + (uint32_t)(wn * 32 + ((matq >> 1) << 3) + rq) * ROWB
        + (uint32_t)((matq & 1) << 4);
    const uint32_t aBl = aBh + (OFF_BL - OFF_BH);

    for (int chunk = 0; chunk < NCHUNK; ++chunk) {
        __syncthreads();   // staging done / previous MMA reads done

        int o[8];
        #pragma unroll
        for (int t = 0; t < 8; ++t) o[t] = lut[chunk * KCH + u * 8 + t];

        // ---- build A_hi / A_lo: 64m x 64k ----
        #pragma unroll
        for (int j = 0; j < 2; ++j) {
            const int m    = j * 32 + mg;
            const int base = (m >> 4) * RAW_C + (m & 15);
            float v[8];
            #pragma unroll
            for (int t = 0; t < 8; ++t) v[t] = rawf[base + o[t]];
            uint32_t hp[4], lp[4];
            #pragma unroll
            for (int t = 0; t < 4; ++t)
                split2(v[2 * t], v[2 * t + 1], hp[t], lp[t]);
            const uint32_t byte = (uint32_t)m * ROWB + (uint32_t)u * 16u;
            *(uint4*)(sm + OFF_AH + byte) = *(uint4*)hp;
            *(uint4*)(sm + OFF_AL + byte) = *(uint4*)lp;
        }

        // ---- copy pre-converted B tiles ----
        {
            const uint4* bsh = ((const uint4*)Bh_g) + chunk * 512;
            const uint4* bsl = ((const uint4*)Bl_g) + chunk * 512;
            #pragma unroll
            for (int e = tid; e < 512; e += 256) {
                const uint32_t dst = (uint32_t)(e >> 3) * ROWB + (uint32_t)(e & 7) * 16u;
                *(uint4*)(sm + OFF_BH + dst) = bsh[e];
                *(uint4*)(sm + OFF_BL + dst) = bsl[e];
            }
        }

        __syncthreads();

        // ---- MMA: 4 k16-steps, 3 passes (Ah*Bh + Ah*Bl + Al*Bh) ----
        #pragma unroll
        for (int ks = 0; ks < 4; ++ks) {
            const uint32_t ko = (uint32_t)ks * 32u;
            uint32_t ah[4], al[4], bh[8], bl[8];
            ldmx4(ah, aAh + ko);
            ldmx4(al, aAl + ko);
            ldmx4(bh,     aBh + ko);
            ldmx4(bh + 4, aBh + 16u * ROWB + ko);
            ldmx4(bl,     aBl + ko);
            ldmx4(bl + 4, aBl + 16u * ROWB + ko);
            #pragma unroll
            for (int g = 0; g < 4; ++g) {
                mma_bf16(acc[g], ah, bh + 2 * g);
                mma_bf16(acc[g], ah, bl + 2 * g);
                mma_bf16(acc[g], al, bh + 2 * g);
            }
        }
    }

    // ---- epilogue: bias + store ----
    #pragma unroll
    for (int half = 0; half < 2; ++half) {
        const int gy = row0 + wm;
        const int gx = col0 + grp + half * 8;
        float* op = &out[((b * OUT_C) * HH + gy) * WW + gx];
        #pragma unroll
        for (int g = 0; g < 4; ++g) {
            const int n = wn * 32 + g * 8 + tid4 * 2;
            op[n * (HH * WW)]       = acc[g][half * 2]     + biass[n];
            op[(n + 1) * (HH * WW)] = acc[g][half * 2 + 1] + biass[n + 1];
        }
    }
}

extern "C" void kernel_launch(void* const* d_in, const int* in_sizes, int n_in,
                              void* d_out, int out_size)
{
    const float* x    = (const float*)d_in[0];
    const float* wgt  = (const float*)d_in[1];
    const float* bias = (const float*)d_in[2];
    float* out        = (float*)d_out;

    cudaFuncSetAttribute(conv3x3_hmma_kernel,
                         cudaFuncAttributeMaxDynamicSharedMemorySize, SMEM_BYTES);

    prep_weights_kernel<<<(NCHUNK * 64 * KCH + 255) / 256, 256>>>(wgt);

    dim3 grid(WW / TCOLS, HH / TROWS, NB);   // (7, 28, 2) = 392 CTAs
    conv3x3_hmma_kernel<<<grid, 256, SMEM_BYTES>>>(x, bias, out);
}